// round 12
// baseline (speedup 1.0000x reference)
#include <cuda_runtime.h>
#include <cstdint>

#define B_      2048
#define D_      512
#define NA_     512
#define CAP_    32
#define NVMAX_  8
#define NSL_    2
#define ROWS_T  16                   // rows per tile (full 512 cols each)
#define NT_     16                   // tiles per pass (256 rows per CTA)
#define PITCH4_ 129                  // float4 pitch per row (128 + 1 pad)
#define TILE4_  (ROWS_T * PITCH4_)   // 2064 float4 per buffer
#define BUF4_   (2 * TILE4_)         // 4128 float4 (double buffer)
#define SMEMB_  ((BUF4_ + NVMAX_ * 128) * 16)   // 82432 B -> 2 CTAs/SM

// ---------------- device scratch (zero-init at load; consumer-zeroed) ----
__device__ int g_counts[NSL_][NA_];
__device__ int g_buckets[NA_ * CAP_];

// ---------------- kernel 1: bucket by attribute ----------------
__global__ void k_bucket(const int* __restrict__ attrs) {
    int b = blockIdx.x * blockDim.x + threadIdx.x;
    if (b >= B_) return;
    int a = attrs[b];
    int pos = atomicAdd(&g_counts[0][a], 1);
    atomicAdd(&g_counts[1][a], 1);
    if (pos < CAP_) g_buckets[a * CAP_ + pos] = b;
}

// ---------------- cp.async helpers ----------------
__device__ __forceinline__ void cp16(uint32_t saddr, const void* gaddr) {
    asm volatile("cp.async.cg.shared.global [%0], [%1], 16;"
                 :: "r"(saddr), "l"(gaddr));
}
__device__ __forceinline__ void cp_commit() {
    asm volatile("cp.async.commit_group;");
}
template <int N>
__device__ __forceinline__ void cp_wait() {
    asm volatile("cp.async.wait_group %0;" :: "n"(N));
}

// stage one tile: 16 FULL rows = 32 KB CONTIGUOUS global memory.
// Warp-instr n reads a contiguous 512B span (perfect coalescing / DRAM bursts).
// smem addr4 = row*129 + kg*8 + (i ^ (kg&7))  — 4-way spread = 4 wf (optimal).
__device__ __forceinline__ void issue_tile(
    uint32_t sbuf, const float4* __restrict__ gtile, int warp, int lane)
{
#pragma unroll
    for (int n = 0; n < 8; n++) {
        int G   = warp * 256 + n * 32 + lane;    // 0..2047 contiguous f4
        int row = G >> 7;
        int rem = G & 127;
        int kg  = rem >> 3;
        int i   = rem & 7;
        uint32_t a4 = (uint32_t)(row * PITCH4_ + kg * 8 + (i ^ (kg & 7)));
        cp16(sbuf + a4 * 16, gtile + G);
    }
    cp_commit();
}

// ---------------- per-CTA pass: 256 rows x 512 k x NV samples ------------
// thread = (row_r = tid>>4, kg = tid&15): 32 k of one row per tile;
// full row completes per tile -> 4-shfl reduce, lane kg==j stores sample j.
template <int NV>
__device__ __forceinline__ void run_pass(
    const float4* __restrict__ g,           // CTA slice base (f4)
    float4* __restrict__ b0, float4* __restrict__ b1,
    uint32_t s0, uint32_t s1,
    const float4* __restrict__ sv4,         // smem vectors [NV][128]
    const int* __restrict__ ssamp,
    int nv, float* __restrict__ out, int grow0, int tid)
{
    int warp  = tid >> 5;
    int lane  = tid & 31;
    int row_r = tid >> 4;
    int kg    = tid & 15;

    issue_tile(s0, g,        warp, lane);
    issue_tile(s1, g + 2048, warp, lane);

#pragma unroll 1
    for (int T = 0; T < NT_; T++) {
        if (T < NT_ - 1) cp_wait<1>(); else cp_wait<0>();
        __syncthreads();                          // tile visible to all
        const float4* buf = (T & 1) ? b1 : b0;

        float acc[NV];
#pragma unroll
        for (int j = 0; j < NV; j++) acc[j] = 0.0f;

#pragma unroll
        for (int i = 0; i < 8; i++) {
            float4 m = buf[row_r * PITCH4_ + kg * 8 + (i ^ (kg & 7))];
#pragma unroll
            for (int j = 0; j < NV; j++) {
                float4 v = sv4[j * 128 + kg * 8 + i];
                acc[j] = fmaf(m.x, v.x, acc[j]);
                acc[j] = fmaf(m.y, v.y, acc[j]);
                acc[j] = fmaf(m.z, v.z, acc[j]);
                acc[j] = fmaf(m.w, v.w, acc[j]);
            }
        }
        __syncthreads();                          // all reads done
        if (T + 2 < NT_)
            issue_tile((T & 1) ? s1 : s0, g + (T + 2) * 2048, warp, lane);

        int row = grow0 + T * ROWS_T + row_r;
#pragma unroll
        for (int j = 0; j < NV; j++) {
            float x = acc[j];
            x += __shfl_xor_sync(0xffffffffu, x, 8);
            x += __shfl_xor_sync(0xffffffffu, x, 4);
            x += __shfl_xor_sync(0xffffffffu, x, 2);
            x += __shfl_xor_sync(0xffffffffu, x, 1);
            if (j < nv && kg == j)
                out[(size_t)ssamp[j] * D_ + row] = fmaxf(x, 0.0f);
        }
    }
}

// ---------------- kernel 2: per-attribute matvec ------------------------
// grid = (NA_, NSL_), 256 threads. CTA owns 256 contiguous rows.
__global__ __launch_bounds__(256) void k_compute(
    const int*   __restrict__ attrs,
    const int*   __restrict__ objs,
    const float* __restrict__ attr_ops,
    const float* __restrict__ obj_emb,
    float*       __restrict__ out)
{
    extern __shared__ float4 smem4[];
    float4* b0  = smem4;                     // tile buffer 0 (33 KB)
    float4* b1  = smem4 + TILE4_;            // tile buffer 1 (33 KB)
    float4* sv4 = smem4 + BUF4_;             // vectors (16 KB)
    __shared__ int ssamp[NVMAX_];

    int tid = threadIdx.x;
    int a   = blockIdx.x;
    int y   = blockIdx.y;

    int cnt = g_counts[y][a];
    int grow0 = y * 256;
    const float4* g =
        (const float4*)(attr_ops + (size_t)a * D_ * D_) + (size_t)grow0 * 128;
    uint32_t s0 = (uint32_t)__cvta_generic_to_shared(b0);
    uint32_t s1 = (uint32_t)__cvta_generic_to_shared(b1);

    if (cnt <= CAP_) {
        for (int base = 0; base < cnt; base += NVMAX_) {
            int nv = cnt - base;
            if (nv > NVMAX_) nv = NVMAX_;
            int NVsel = (nv <= 1) ? 1 : (nv <= 2) ? 2 : (nv <= 4) ? 4 : 8;

            __syncthreads();                 // prior pass done with sv/ssamp
            if (tid < nv) ssamp[tid] = g_buckets[a * CAP_ + base + tid];
            __syncthreads();

            for (int u = tid; u < NVsel * 128; u += 256) {
                int j = u >> 7;
                float4 val = make_float4(0.f, 0.f, 0.f, 0.f);
                if (j < nv)
                    val = ((const float4*)(obj_emb + (size_t)objs[ssamp[j]] * D_))[u & 127];
                sv4[u] = val;
            }
            __syncthreads();

            switch (NVsel) {
                case 1: run_pass<1>(g, b0, b1, s0, s1, sv4, ssamp, nv, out, grow0, tid); break;
                case 2: run_pass<2>(g, b0, b1, s0, s1, sv4, ssamp, nv, out, grow0, tid); break;
                case 4: run_pass<4>(g, b0, b1, s0, s1, sv4, ssamp, nv, out, grow0, tid); break;
                default: run_pass<8>(g, b0, b1, s0, s1, sv4, ssamp, nv, out, grow0, tid); break;
            }
        }
    } else {
        // overflow (cnt > CAP): uniform in-CTA scan — correctness safety net,
        // never taken for this distribution.
        int nb = 0;
        for (int b = 0; b < B_; b++) {
            if (attrs[b] == a) {
                __syncthreads();
                if (tid == 0) ssamp[nb] = b;
                nb++;
                if (nb == NVMAX_) {
                    __syncthreads();
                    for (int u = tid; u < NVMAX_ * 128; u += 256) {
                        int j = u >> 7;
                        sv4[u] = ((const float4*)(obj_emb +
                                   (size_t)objs[ssamp[j]] * D_))[u & 127];
                    }
                    __syncthreads();
                    run_pass<8>(g, b0, b1, s0, s1, sv4, ssamp, NVMAX_, out, grow0, tid);
                    nb = 0;
                }
            }
        }
        if (nb > 0) {
            __syncthreads();
            for (int u = tid; u < NVMAX_ * 128; u += 256) {
                int j = u >> 7;
                float4 val = make_float4(0.f, 0.f, 0.f, 0.f);
                if (j < nb)
                    val = ((const float4*)(obj_emb + (size_t)objs[ssamp[j]] * D_))[u & 127];
                sv4[u] = val;
            }
            __syncthreads();
            run_pass<8>(g, b0, b1, s0, s1, sv4, ssamp, nb, out, grow0, tid);
        }
    }

    // restore clean state for next graph replay (sole reader of this slot)
    if (tid == 0) g_counts[y][a] = 0;
}

// ---------------- launch -------------------------------------------------
extern "C" void kernel_launch(void* const* d_in, const int* in_sizes, int n_in,
                              void* d_out, int out_size)
{
    const int*   attrs    = (const int*)d_in[0];
    const int*   objs     = (const int*)d_in[1];
    const float* attr_ops = (const float*)d_in[2];
    const float* obj_emb  = (const float*)d_in[3];
    float*       out      = (float*)d_out;

    cudaFuncSetAttribute(k_compute,
                         cudaFuncAttributeMaxDynamicSharedMemorySize, SMEMB_);

    k_bucket<<<(B_ + 255) / 256, 256>>>(attrs);
    k_compute<<<dim3(NA_, NSL_), 256, SMEMB_>>>(attrs, objs, attr_ops, obj_emb, out);
}

// round 13
// speedup vs baseline: 5.7879x; 5.7879x over previous
#include <cuda_runtime.h>
#include <cstdint>

#define B_      2048
#define D_      512
#define NA_     512
#define NVMAX_  8
#define WARPS_  8
#define NSL_    2
#define RPW_    32                  // rows per warp: 512 / (8 warps * 2 slices)
#define NCH_    32                  // k-chunks per pass (512/16)
#define SLOT4_  (RPW_ * 4)          // 128 float4 per slot (32 rows x 16 k = 2KB)
#define RING4_  (2 * SLOT4_)        // 256 float4 per warp (2 slots)
#define SV4OFF_ (WARPS_ * RING4_)   // 2048
#define SMEMB_  ((SV4OFF_ + NVMAX_ * 128) * 16)   // 49152 B dynamic

// ---------------- cp.async helpers ----------------
__device__ __forceinline__ void cp16(uint32_t saddr, const void* gaddr) {
    asm volatile("cp.async.cg.shared.global [%0], [%1], 16;"
                 :: "r"(saddr), "l"(gaddr));
}
__device__ __forceinline__ void cp_commit() {
    asm volatile("cp.async.commit_group;");
}
template <int N>
__device__ __forceinline__ void cp_wait() {
    asm volatile("cp.async.wait_group %0;" :: "n"(N));
}

// stage one k-chunk (32 rows x 16 k = 2KB) into a swizzled smem slot.
// (verbatim from the 116us R10 kernel — proven correct & fastest so far)
__device__ __forceinline__ void issue_chunk(
    uint32_t sslot, const float4* __restrict__ gbase, int c, int lane)
{
    int sub = lane >> 2;        // 0..7 row-within-group
    int off = lane & 3;         // 0..3 float4-within-chunk-row
    const float4* g = gbase + c * 4 + off;
#pragma unroll
    for (int i = 0; i < 4; i++) {
        int row = i * 8 + sub;
        uint32_t a4 = (uint32_t)(row * 4 + (off ^ (row & 3)));
        cp16(sslot + a4 * 16, g + (size_t)row * 128);
    }
    cp_commit();
}

// reader: slot[lane*4 + (k4 ^ (lane&3))] — XOR bijective, conflict-free;
// vector read uniform across warp -> true broadcast (lane = row mapping)
template <int NV>
__device__ __forceinline__ void chunk_fma(
    const float4* __restrict__ sp, const float4* __restrict__ sv4,
    float* __restrict__ acc, int c, int lane)
{
#pragma unroll
    for (int k4 = 0; k4 < 4; k4++) {
        float4 m = sp[lane * 4 + (k4 ^ (lane & 3))];
#pragma unroll
        for (int j = 0; j < NV; j++) {
            float4 v = sv4[j * 128 + c * 4 + k4];     // broadcast, 1 wf
            acc[j] = fmaf(m.x, v.x, acc[j]);
            acc[j] = fmaf(m.y, v.y, acc[j]);
            acc[j] = fmaf(m.z, v.z, acc[j]);
            acc[j] = fmaf(m.w, v.w, acc[j]);
        }
    }
}

// ---------------- per-warp pass: depth-2 cp.async ring (R10 core) ---------
template <int NV>
__device__ __forceinline__ void run_pass(
    const float4* __restrict__ gbase,
    float4* __restrict__ slot0, float4* __restrict__ slot1,
    uint32_t s0, uint32_t s1,
    const float4* __restrict__ sv4,
    const int* __restrict__ ssamp,
    int nv, float* __restrict__ out, int grow0, int lane)
{
    float acc[NV];
#pragma unroll
    for (int j = 0; j < NV; j++) acc[j] = 0.0f;

    issue_chunk(s0, gbase, 0, lane);
    issue_chunk(s1, gbase, 1, lane);

#pragma unroll 1
    for (int c = 0; c < NCH_ - 2; c++) {
        cp_wait<1>();
        __syncwarp();
        chunk_fma<NV>((c & 1) ? slot1 : slot0, sv4, acc, c, lane);
        __syncwarp();
        issue_chunk((c & 1) ? s1 : s0, gbase, c + 2, lane);
    }
    cp_wait<1>(); __syncwarp();
    chunk_fma<NV>(slot0, sv4, acc, NCH_ - 2, lane);
    cp_wait<0>(); __syncwarp();
    chunk_fma<NV>(slot1, sv4, acc, NCH_ - 1, lane);

    int row = grow0 + lane;
#pragma unroll
    for (int j = 0; j < NV; j++)
        if (j < nv)
            out[(size_t)ssamp[j] * D_ + row] = fmaxf(acc[j], 0.0f);
}

// ---------------- single kernel: scan + per-attribute matvec -------------
// grid = (NA_, NSL_, 2): x=attr, y=256-row slice, z=sample-window parity.
// No device scratch, no bucket kernel: each CTA ballot-scans attrs (smem-
// cached) for its own deterministic sample window. z splits multi-pass
// buckets into parallel CTAs -> uniform CTA work, no straggler tail.
__global__ __launch_bounds__(256, 4) void k_compute(
    const int*   __restrict__ attrs,
    const int*   __restrict__ objs,
    const float* __restrict__ attr_ops,
    const float* __restrict__ obj_emb,
    float*       __restrict__ out)
{
    extern __shared__ float4 smem4[];
    float4* ring = smem4;                          // [8][2][128] f4 = 32 KB
    float4* sv4  = smem4 + SV4OFF_;                // [8][128]    f4 = 16 KB
    __shared__ int sattr[B_];                      // 8 KB
    __shared__ int ssamp[NVMAX_];
    __shared__ int scnt;

    int tid  = threadIdx.x;
    int lane = tid & 31;
    int warp = tid >> 5;
    int a    = blockIdx.x;
    int y    = blockIdx.y;
    int z    = blockIdx.z;

    // cache attrs in smem (coalesced, one round)
    for (int u = tid; u < B_; u += 256) sattr[u] = attrs[u];

    int grow0 = y * (WARPS_ * RPW_) + warp * RPW_;
    const float4* Mw =
        (const float4*)(attr_ops + (size_t)a * D_ * D_) + (size_t)grow0 * 128;
    float4*  slot0 = ring + warp * RING4_;
    float4*  slot1 = slot0 + SLOT4_;
    uint32_t s0 = (uint32_t)__cvta_generic_to_shared(slot0);
    uint32_t s1 = (uint32_t)__cvta_generic_to_shared(slot1);

    int base = z * NVMAX_;
    for (;;) {
        // ---- deterministic ballot scan: samples [base, base+8) ----
        __syncthreads();                 // scan/vector writes vs prior readers
        if (tid < 32) {
            int c = 0;
#pragma unroll 4
            for (int it = 0; it < B_ / 32; it++) {
                bool m = (sattr[it * 32 + lane] == a);
                unsigned msk = __ballot_sync(0xffffffffu, m);
                if (m) {
                    int j = c + __popc(msk & ((1u << lane) - 1u));
                    int rel = j - base;
                    if (rel >= 0 && rel < NVMAX_) ssamp[rel] = it * 32 + lane;
                }
                c += __popc(msk);
            }
            if (lane == 0) scnt = c;
        }
        __syncthreads();

        int nv = scnt - base;
        if (nv <= 0) break;
        if (nv > NVMAX_) nv = NVMAX_;
        int NVsel = (nv <= 1) ? 1 : (nv <= 2) ? 2 : (nv <= 4) ? 4 : 8;

        // ---- load vectors, zero-padded to NVsel ----
        for (int u = tid; u < NVsel * 128; u += 256) {
            int j = u >> 7;
            float4 val = make_float4(0.f, 0.f, 0.f, 0.f);
            if (j < nv)
                val = ((const float4*)(obj_emb + (size_t)objs[ssamp[j]] * D_))[u & 127];
            sv4[u] = val;
        }
        __syncthreads();

        switch (NVsel) {
            case 1: run_pass<1>(Mw, slot0, slot1, s0, s1, sv4, ssamp, nv, out, grow0, lane); break;
            case 2: run_pass<2>(Mw, slot0, slot1, s0, s1, sv4, ssamp, nv, out, grow0, lane); break;
            case 4: run_pass<4>(Mw, slot0, slot1, s0, s1, sv4, ssamp, nv, out, grow0, lane); break;
            default: run_pass<8>(Mw, slot0, slot1, s0, s1, sv4, ssamp, nv, out, grow0, lane); break;
        }

        base += 2 * NVMAX_;              // interleaved windows across z
    }
}

// ---------------- launch -------------------------------------------------
extern "C" void kernel_launch(void* const* d_in, const int* in_sizes, int n_in,
                              void* d_out, int out_size)
{
    const int*   attrs    = (const int*)d_in[0];
    const int*   objs     = (const int*)d_in[1];
    const float* attr_ops = (const float*)d_in[2];
    const float* obj_emb  = (const float*)d_in[3];
    float*       out      = (float*)d_out;

    cudaFuncSetAttribute(k_compute,
                         cudaFuncAttributeMaxDynamicSharedMemorySize, SMEMB_);

    k_compute<<<dim3(NA_, NSL_, 2), 256, SMEMB_>>>(attrs, objs, attr_ops, obj_emb, out);
}

// round 14
// speedup vs baseline: 7.1748x; 1.2396x over previous
#include <cuda_runtime.h>
#include <cstdint>

#define B_      2048
#define D_      512
#define NA_     512
#define CAP_    32
#define NVMAX_  8
#define WARPS_  4
#define NSL_    4
#define THR_    128
#define RPW_    32                  // rows per warp: 512 / (4 warps * 4 slices)
#define NCH_    32                  // k-chunks per pass (512/16)
#define SLOT4_  (RPW_ * 4)          // 128 float4 per slot (32 rows x 16 k = 2KB)
#define RING4_  (2 * SLOT4_)        // 256 float4 per warp (2 slots)
#define SV4OFF_ (WARPS_ * RING4_)   // 1024
#define SMEMB_  ((SV4OFF_ + NVMAX_ * 128) * 16)   // 32768 B -> ~7 CTAs/SM

// ---------------- device scratch (zero-init at load; consumer-zeroed) ----
__device__ int g_counts[NSL_][NA_];
__device__ int g_buckets[NA_ * CAP_];

// ---------------- kernel 1: bucket by attribute (no zero phase) ----------
__global__ void k_bucket(const int* __restrict__ attrs) {
    int b = blockIdx.x * blockDim.x + threadIdx.x;
    if (b >= B_) return;
    int a = attrs[b];
    int pos = atomicAdd(&g_counts[0][a], 1);
    atomicAdd(&g_counts[1][a], 1);
    atomicAdd(&g_counts[2][a], 1);
    atomicAdd(&g_counts[3][a], 1);
    if (pos < CAP_) g_buckets[a * CAP_ + pos] = b;
}

// ---------------- cp.async helpers ----------------
__device__ __forceinline__ void cp16(uint32_t saddr, const void* gaddr) {
    asm volatile("cp.async.cg.shared.global [%0], [%1], 16;"
                 :: "r"(saddr), "l"(gaddr));
}
__device__ __forceinline__ void cp_commit() {
    asm volatile("cp.async.commit_group;");
}
template <int N>
__device__ __forceinline__ void cp_wait() {
    asm volatile("cp.async.wait_group %0;" :: "n"(N));
}

// stage one k-chunk (32 rows x 16 k = 2KB) into a swizzled smem slot.
// (verbatim from the proven R10 kernel)
__device__ __forceinline__ void issue_chunk(
    uint32_t sslot, const float4* __restrict__ gbase, int c, int lane)
{
    int sub = lane >> 2;        // 0..7 row-within-group
    int off = lane & 3;         // 0..3 float4-within-chunk-row
    const float4* g = gbase + c * 4 + off;
#pragma unroll
    for (int i = 0; i < 4; i++) {
        int row = i * 8 + sub;
        uint32_t a4 = (uint32_t)(row * 4 + (off ^ (row & 3)));
        cp16(sslot + a4 * 16, g + (size_t)row * 128);
    }
    cp_commit();
}

// reader: slot[lane*4 + (k4 ^ (lane&3))] — XOR bijective, conflict-free;
// vector read uniform across warp -> true broadcast (lane = row mapping)
template <int NV>
__device__ __forceinline__ void chunk_fma(
    const float4* __restrict__ sp, const float4* __restrict__ sv4,
    float* __restrict__ acc, int c, int lane)
{
#pragma unroll
    for (int k4 = 0; k4 < 4; k4++) {
        float4 m = sp[lane * 4 + (k4 ^ (lane & 3))];
#pragma unroll
        for (int j = 0; j < NV; j++) {
            float4 v = sv4[j * 128 + c * 4 + k4];     // broadcast, 1 wf
            acc[j] = fmaf(m.x, v.x, acc[j]);
            acc[j] = fmaf(m.y, v.y, acc[j]);
            acc[j] = fmaf(m.z, v.z, acc[j]);
            acc[j] = fmaf(m.w, v.w, acc[j]);
        }
    }
}

// ---------------- per-warp pass: depth-2 cp.async ring (R10 core) ---------
template <int NV>
__device__ __forceinline__ void run_pass(
    const float4* __restrict__ gbase,
    float4* __restrict__ slot0, float4* __restrict__ slot1,
    uint32_t s0, uint32_t s1,
    const float4* __restrict__ sv4,
    const int* __restrict__ ssamp,
    int nv, float* __restrict__ out, int grow0, int lane)
{
    float acc[NV];
#pragma unroll
    for (int j = 0; j < NV; j++) acc[j] = 0.0f;

    issue_chunk(s0, gbase, 0, lane);
    issue_chunk(s1, gbase, 1, lane);

#pragma unroll 1
    for (int c = 0; c < NCH_ - 2; c++) {
        cp_wait<1>();
        __syncwarp();
        chunk_fma<NV>((c & 1) ? slot1 : slot0, sv4, acc, c, lane);
        __syncwarp();
        issue_chunk((c & 1) ? s1 : s0, gbase, c + 2, lane);
    }
    cp_wait<1>(); __syncwarp();
    chunk_fma<NV>(slot0, sv4, acc, NCH_ - 2, lane);
    cp_wait<0>(); __syncwarp();
    chunk_fma<NV>(slot1, sv4, acc, NCH_ - 1, lane);

    int row = grow0 + lane;
#pragma unroll
    for (int j = 0; j < NV; j++)
        if (j < nv)
            out[(size_t)ssamp[j] * D_ + row] = fmaxf(acc[j], 0.0f);
}

// ---------------- kernel 2: per-attribute matvec ------------------------
// grid = (NA_, NSL_), 128 threads (4 warps). CTA owns 128 contiguous rows
// (~31us work quantum -> finer wave packing, smaller ragged tail).
__global__ __launch_bounds__(THR_) void k_compute(
    const int*   __restrict__ attrs,
    const int*   __restrict__ objs,
    const float* __restrict__ attr_ops,
    const float* __restrict__ obj_emb,
    float*       __restrict__ out)
{
    extern __shared__ float4 smem4[];
    float4* ring = smem4;                          // [4][2][128] f4 = 16 KB
    float4* sv4  = smem4 + SV4OFF_;                // [8][128]    f4 = 16 KB
    __shared__ int ssamp[NVMAX_];

    int tid  = threadIdx.x;
    int lane = tid & 31;
    int warp = tid >> 5;
    int a    = blockIdx.x;
    int y    = blockIdx.y;

    int cnt = g_counts[y][a];

    int grow0 = y * (WARPS_ * RPW_) + warp * RPW_;
    const float4* Mw =
        (const float4*)(attr_ops + (size_t)a * D_ * D_) + (size_t)grow0 * 128;
    float4*  slot0 = ring + warp * RING4_;
    float4*  slot1 = slot0 + SLOT4_;
    uint32_t s0 = (uint32_t)__cvta_generic_to_shared(slot0);
    uint32_t s1 = (uint32_t)__cvta_generic_to_shared(slot1);

    if (cnt <= CAP_) {
        for (int base = 0; base < cnt; base += NVMAX_) {
            int nv = cnt - base;
            if (nv > NVMAX_) nv = NVMAX_;
            int NVsel = (nv <= 1) ? 1 : (nv <= 2) ? 2 : (nv <= 4) ? 4 : 8;

            __syncthreads();                  // prior pass done reading sv4
            if (tid < nv) ssamp[tid] = g_buckets[a * CAP_ + base + tid];
            __syncthreads();

            for (int u = tid; u < NVsel * 128; u += THR_) {
                int j = u >> 7;
                float4 val = make_float4(0.f, 0.f, 0.f, 0.f);
                if (j < nv)
                    val = ((const float4*)(obj_emb + (size_t)objs[ssamp[j]] * D_))[u & 127];
                sv4[u] = val;
            }
            __syncthreads();

            switch (NVsel) {
                case 1: run_pass<1>(Mw, slot0, slot1, s0, s1, sv4, ssamp, nv, out, grow0, lane); break;
                case 2: run_pass<2>(Mw, slot0, slot1, s0, s1, sv4, ssamp, nv, out, grow0, lane); break;
                case 4: run_pass<4>(Mw, slot0, slot1, s0, s1, sv4, ssamp, nv, out, grow0, lane); break;
                default: run_pass<8>(Mw, slot0, slot1, s0, s1, sv4, ssamp, nv, out, grow0, lane); break;
            }
        }
    } else {
        // overflow (cnt > CAP): uniform in-CTA scan — correctness safety net,
        // never taken for Poisson(4) buckets.
        int nb = 0;
        for (int b = 0; b < B_; b++) {
            if (attrs[b] == a) {
                __syncthreads();
                if (tid == 0) ssamp[nb] = b;
                nb++;
                if (nb == NVMAX_) {
                    __syncthreads();
                    for (int u = tid; u < NVMAX_ * 128; u += THR_) {
                        int j = u >> 7;
                        sv4[u] = ((const float4*)(obj_emb +
                                   (size_t)objs[ssamp[j]] * D_))[u & 127];
                    }
                    __syncthreads();
                    run_pass<8>(Mw, slot0, slot1, s0, s1, sv4, ssamp, NVMAX_, out, grow0, lane);
                    nb = 0;
                }
            }
        }
        if (nb > 0) {
            __syncthreads();
            for (int u = tid; u < NVMAX_ * 128; u += THR_) {
                int j = u >> 7;
                float4 val = make_float4(0.f, 0.f, 0.f, 0.f);
                if (j < nb)
                    val = ((const float4*)(obj_emb + (size_t)objs[ssamp[j]] * D_))[u & 127];
                sv4[u] = val;
            }
            __syncthreads();
            run_pass<8>(Mw, slot0, slot1, s0, s1, sv4, ssamp, nb, out, grow0, lane);
        }
    }

    // restore clean state for next graph replay (sole reader of this slot)
    if (tid == 0) g_counts[y][a] = 0;
}

// ---------------- launch -------------------------------------------------
extern "C" void kernel_launch(void* const* d_in, const int* in_sizes, int n_in,
                              void* d_out, int out_size)
{
    const int*   attrs    = (const int*)d_in[0];
    const int*   objs     = (const int*)d_in[1];
    const float* attr_ops = (const float*)d_in[2];
    const float* obj_emb  = (const float*)d_in[3];
    float*       out      = (float*)d_out;

    cudaFuncSetAttribute(k_compute,
                         cudaFuncAttributeMaxDynamicSharedMemorySize, SMEMB_);

    k_bucket<<<(B_ + 255) / 256, 256>>>(attrs);
    k_compute<<<dim3(NA_, NSL_), THR_, SMEMB_>>>(attrs, objs, attr_ops, obj_emb, out);
}

// round 15
// speedup vs baseline: 7.1769x; 1.0003x over previous
#include <cuda_runtime.h>
#include <cstdint>

#define B_      2048
#define D_      512
#define NA_     512
#define CAP_    32
#define NVMAX_  8
#define WARPS_  4
#define NSL_    4
#define NZ_     2
#define THR_    128
#define RPW_    32                  // rows per warp: 512 / (4 warps * 4 slices)
#define NCH_    32                  // k-chunks per pass (512/16)
#define SLOT4_  (RPW_ * 4)          // 128 float4 per slot (32 rows x 16 k = 2KB)
#define RING4_  (2 * SLOT4_)        // 256 float4 per warp (2 slots)
#define SV4OFF_ (WARPS_ * RING4_)   // 1024
#define SMEMB_  ((SV4OFF_ + NVMAX_ * 128) * 16)   // 32768 B -> ~7 CTAs/SM

// ---------------- device scratch (zero-init at load; consumer-zeroed) ----
// one count copy per (y,z) consumer CTA so each can reset its own slot
__device__ int g_counts[NSL_][NZ_][NA_];
__device__ int g_buckets[NA_ * CAP_];

// ---------------- kernel 1: bucket by attribute (no zero phase) ----------
__global__ void k_bucket(const int* __restrict__ attrs) {
    int b = blockIdx.x * blockDim.x + threadIdx.x;
    if (b >= B_) return;
    int a = attrs[b];
    int pos = atomicAdd(&g_counts[0][0][a], 1);
#pragma unroll
    for (int y = 0; y < NSL_; y++)
#pragma unroll
        for (int z = 0; z < NZ_; z++)
            if (!(y == 0 && z == 0)) atomicAdd(&g_counts[y][z][a], 1);
    if (pos < CAP_) g_buckets[a * CAP_ + pos] = b;
}

// ---------------- cp.async helpers ----------------
__device__ __forceinline__ void cp16(uint32_t saddr, const void* gaddr) {
    asm volatile("cp.async.cg.shared.global [%0], [%1], 16;"
                 :: "r"(saddr), "l"(gaddr));
}
__device__ __forceinline__ void cp_commit() {
    asm volatile("cp.async.commit_group;");
}
template <int N>
__device__ __forceinline__ void cp_wait() {
    asm volatile("cp.async.wait_group %0;" :: "n"(N));
}

// stage one k-chunk (32 rows x 16 k = 2KB) into a swizzled smem slot.
// (verbatim from the proven 111us kernel)
__device__ __forceinline__ void issue_chunk(
    uint32_t sslot, const float4* __restrict__ gbase, int c, int lane)
{
    int sub = lane >> 2;        // 0..7 row-within-group
    int off = lane & 3;         // 0..3 float4-within-chunk-row
    const float4* g = gbase + c * 4 + off;
#pragma unroll
    for (int i = 0; i < 4; i++) {
        int row = i * 8 + sub;
        uint32_t a4 = (uint32_t)(row * 4 + (off ^ (row & 3)));
        cp16(sslot + a4 * 16, g + (size_t)row * 128);
    }
    cp_commit();
}

// reader: slot[lane*4 + (k4 ^ (lane&3))] — XOR bijective, conflict-free;
// vector read uniform across warp -> true broadcast (lane = row mapping)
template <int NV>
__device__ __forceinline__ void chunk_fma(
    const float4* __restrict__ sp, const float4* __restrict__ sv4,
    float* __restrict__ acc, int c, int lane)
{
#pragma unroll
    for (int k4 = 0; k4 < 4; k4++) {
        float4 m = sp[lane * 4 + (k4 ^ (lane & 3))];
#pragma unroll
        for (int j = 0; j < NV; j++) {
            float4 v = sv4[j * 128 + c * 4 + k4];     // broadcast, 1 wf
            acc[j] = fmaf(m.x, v.x, acc[j]);
            acc[j] = fmaf(m.y, v.y, acc[j]);
            acc[j] = fmaf(m.z, v.z, acc[j]);
            acc[j] = fmaf(m.w, v.w, acc[j]);
        }
    }
}

// ---------------- per-warp pass: depth-2 cp.async ring --------------------
template <int NV>
__device__ __forceinline__ void run_pass(
    const float4* __restrict__ gbase,
    float4* __restrict__ slot0, float4* __restrict__ slot1,
    uint32_t s0, uint32_t s1,
    const float4* __restrict__ sv4,
    const int* __restrict__ ssamp,
    int nv, float* __restrict__ out, int grow0, int lane)
{
    float acc[NV];
#pragma unroll
    for (int j = 0; j < NV; j++) acc[j] = 0.0f;

    issue_chunk(s0, gbase, 0, lane);
    issue_chunk(s1, gbase, 1, lane);

#pragma unroll 1
    for (int c = 0; c < NCH_ - 2; c++) {
        cp_wait<1>();
        __syncwarp();
        chunk_fma<NV>((c & 1) ? slot1 : slot0, sv4, acc, c, lane);
        __syncwarp();
        issue_chunk((c & 1) ? s1 : s0, gbase, c + 2, lane);
    }
    cp_wait<1>(); __syncwarp();
    chunk_fma<NV>(slot0, sv4, acc, NCH_ - 2, lane);
    cp_wait<0>(); __syncwarp();
    chunk_fma<NV>(slot1, sv4, acc, NCH_ - 1, lane);

    int row = grow0 + lane;
#pragma unroll
    for (int j = 0; j < NV; j++)
        if (j < nv)
            out[(size_t)ssamp[j] * D_ + row] = fmaxf(acc[j], 0.0f);
}

// ---------------- kernel 2: per-attribute matvec ------------------------
// grid = (NA_, NSL_, NZ_), 128 threads. CTA owns 128 contiguous rows and
// sample windows z*8, z*8+16, ... — multi-pass buckets run in PARALLEL CTAs.
__global__ __launch_bounds__(THR_) void k_compute(
    const int*   __restrict__ attrs,
    const int*   __restrict__ objs,
    const float* __restrict__ attr_ops,
    const float* __restrict__ obj_emb,
    float*       __restrict__ out)
{
    extern __shared__ float4 smem4[];
    float4* ring = smem4;                          // [4][2][128] f4 = 16 KB
    float4* sv4  = smem4 + SV4OFF_;                // [8][128]    f4 = 16 KB
    __shared__ int ssamp[NVMAX_];

    int tid  = threadIdx.x;
    int lane = tid & 31;
    int warp = tid >> 5;
    int a    = blockIdx.x;
    int y    = blockIdx.y;
    int z    = blockIdx.z;

    int cnt = g_counts[y][z][a];

    int grow0 = y * (WARPS_ * RPW_) + warp * RPW_;
    const float4* Mw =
        (const float4*)(attr_ops + (size_t)a * D_ * D_) + (size_t)grow0 * 128;
    float4*  slot0 = ring + warp * RING4_;
    float4*  slot1 = slot0 + SLOT4_;
    uint32_t s0 = (uint32_t)__cvta_generic_to_shared(slot0);
    uint32_t s1 = (uint32_t)__cvta_generic_to_shared(slot1);

    if (cnt <= CAP_) {
        for (int base = z * NVMAX_; base < cnt; base += NZ_ * NVMAX_) {
            int nv = cnt - base;
            if (nv > NVMAX_) nv = NVMAX_;
            int NVsel = (nv <= 1) ? 1 : (nv <= 2) ? 2 : (nv <= 4) ? 4 : 8;

            __syncthreads();                  // prior pass done reading sv4
            if (tid < nv) ssamp[tid] = g_buckets[a * CAP_ + base + tid];
            __syncthreads();

            for (int u = tid; u < NVsel * 128; u += THR_) {
                int j = u >> 7;
                float4 val = make_float4(0.f, 0.f, 0.f, 0.f);
                if (j < nv)
                    val = ((const float4*)(obj_emb + (size_t)objs[ssamp[j]] * D_))[u & 127];
                sv4[u] = val;
            }
            __syncthreads();

            switch (NVsel) {
                case 1: run_pass<1>(Mw, slot0, slot1, s0, s1, sv4, ssamp, nv, out, grow0, lane); break;
                case 2: run_pass<2>(Mw, slot0, slot1, s0, s1, sv4, ssamp, nv, out, grow0, lane); break;
                case 4: run_pass<4>(Mw, slot0, slot1, s0, s1, sv4, ssamp, nv, out, grow0, lane); break;
                default: run_pass<8>(Mw, slot0, slot1, s0, s1, sv4, ssamp, nv, out, grow0, lane); break;
            }
        }
    } else {
        // overflow (cnt > CAP): uniform in-CTA scan, z-interleaved batches —
        // correctness safety net, never taken for Poisson(4) buckets.
        int nb = 0, bi = 0;
        for (int b = 0; b < B_; b++) {
            if (attrs[b] == a) {
                __syncthreads();
                if (tid == 0) ssamp[nb] = b;
                nb++;
                if (nb == NVMAX_) {
                    if ((bi & (NZ_ - 1)) == z) {
                        __syncthreads();
                        for (int u = tid; u < NVMAX_ * 128; u += THR_) {
                            int j = u >> 7;
                            sv4[u] = ((const float4*)(obj_emb +
                                       (size_t)objs[ssamp[j]] * D_))[u & 127];
                        }
                        __syncthreads();
                        run_pass<8>(Mw, slot0, slot1, s0, s1, sv4, ssamp,
                                    NVMAX_, out, grow0, lane);
                    }
                    nb = 0; bi++;
                }
            }
        }
        if (nb > 0 && (bi & (NZ_ - 1)) == z) {
            __syncthreads();
            for (int u = tid; u < NVMAX_ * 128; u += THR_) {
                int j = u >> 7;
                float4 val = make_float4(0.f, 0.f, 0.f, 0.f);
                if (j < nb)
                    val = ((const float4*)(obj_emb + (size_t)objs[ssamp[j]] * D_))[u & 127];
                sv4[u] = val;
            }
            __syncthreads();
            run_pass<8>(Mw, slot0, slot1, s0, s1, sv4, ssamp, nb, out, grow0, lane);
        }
    }

    // restore clean state for next graph replay (sole reader of this slot)
    if (tid == 0) g_counts[y][z][a] = 0;
}

// ---------------- launch -------------------------------------------------
extern "C" void kernel_launch(void* const* d_in, const int* in_sizes, int n_in,
                              void* d_out, int out_size)
{
    const int*   attrs    = (const int*)d_in[0];
    const int*   objs     = (const int*)d_in[1];
    const float* attr_ops = (const float*)d_in[2];
    const float* obj_emb  = (const float*)d_in[3];
    float*       out      = (float*)d_out;

    cudaFuncSetAttribute(k_compute,
                         cudaFuncAttributeMaxDynamicSharedMemorySize, SMEMB_);

    k_bucket<<<(B_ + 255) / 256, 256>>>(attrs);
    k_compute<<<dim3(NA_, NSL_, NZ_), THR_, SMEMB_>>>(attrs, objs, attr_ops, obj_emb, out);
}